// round 17
// baseline (speedup 1.0000x reference)
#include <cuda_runtime.h>
#include <cuda_bf16.h>
#include <cstdint>

#define NB  16
#define NT  512
#define ND  384
#define F4R (ND / 4)     // 96 float4 per row
#define TPB 4            // tokens per block (one per warp)
#define NCH (NT / TPB)   // 128 blocks per batch

// Token-centric fused kernel: per-block redundant scan of the batch's 512
// durations into smem cum[], then each warp owns one token: load its row once
// (cached — reused), store dur copies with streaming hint (evict-first).
// Zero tail rows striped across all 2048 threads... (all warps of the batch).
__global__ __launch_bounds__(128, 16) void lr_token_kernel(const float* __restrict__ enc,
                                                           const int* __restrict__ dur,
                                                           float* __restrict__ out,
                                                           float* __restrict__ out_tail,
                                                           int has_tail, int max_len,
                                                           int nchunks) {
    __shared__ int s_wsum[4];       // per-warp quad-sum totals
    __shared__ int s_wexcl[4];      // exclusive warp offsets
    __shared__ int s_cum[NT];       // inclusive cumsum of durations

    const int blk   = blockIdx.x;
    const int b     = blk / nchunks;
    const int chunk = blk - b * nchunks;

    const int tid  = threadIdx.x;   // 0..127
    const int wid  = tid >> 5;      // 0..3
    const int lane = tid & 31;

    // ---- scan: thread owns tokens 4*tid .. 4*tid+3 ----
    const int4 d4 = ((const int4*)(dur + b * NT))[tid];
    const int q = d4.x + d4.y + d4.z + d4.w;  // quad sum
    int x = q;
    #pragma unroll
    for (int off = 1; off < 32; off <<= 1) {
        int y = __shfl_up_sync(0xffffffffu, x, off);
        if (lane >= off) x += y;
    }
    if (lane == 31) s_wsum[wid] = x;
    __syncthreads();

    if (wid == 0 && lane < 4) {
        int w = s_wsum[lane];
        int v = w;
        #pragma unroll
        for (int off = 1; off < 4; off <<= 1) {
            int y = __shfl_up_sync(0x0000000fu, v, off);
            if (lane >= off) v += y;
        }
        s_wexcl[lane] = v - w;                // exclusive warp offset
    }
    __syncthreads();

    const int incl3 = s_wexcl[wid] + x;       // cumsum after token 4*tid+3
    const int incl2 = incl3 - d4.w;
    const int incl1 = incl2 - d4.z;
    const int incl0 = incl1 - d4.y;
    s_cum[4 * tid]     = incl0;
    s_cum[4 * tid + 1] = incl1;
    s_cum[4 * tid + 2] = incl2;
    s_cum[4 * tid + 3] = incl3;
    __syncthreads();

    const int mel = s_cum[NT - 1];
    if (has_tail && chunk == 0 && tid == 0) out_tail[b] = (float)mel;

    const float4* __restrict__ base = (const float4*)(enc + (size_t)b * NT * ND);
    float4* __restrict__ out4 = (float4*)(out + (size_t)b * max_len * ND);

    // ---- valid region: warp owns token tok, writes rows [start, end) ----
    const int tok   = chunk * TPB + wid;
    int start = (tok > 0) ? s_cum[tok - 1] : 0;
    int end   = s_cum[tok];
    start = min(start, max_len);
    end   = min(end, max_len);

    if (start < end) {
        const float4* s0 = base + (size_t)tok * F4R;
        const float4 va = s0[lane];
        const float4 vb = s0[lane + 32];
        const float4 vc = s0[lane + 64];
        float4* d = out4 + (size_t)start * F4R;
        for (int p = start; p < end; ++p, d += F4R) {
            __stcs(d + lane, va);             // streaming: evict-first dirty lines
            __stcs(d + lane + 32, vb);
            __stcs(d + lane + 64, vc);
        }
    }

    // ---- zero tail: rows [min(mel,max_len), max_len) striped over 512 warps ----
    const int zstart = min(mel, max_len);
    const int gw = chunk * TPB + wid;         // 0..511 within this batch
    const float4 z = make_float4(0.f, 0.f, 0.f, 0.f);
    for (int r = zstart + gw; r < max_len; r += NT) {
        float4* d = out4 + (size_t)r * F4R;
        __stcs(d + lane, z);
        __stcs(d + lane + 32, z);
        __stcs(d + lane + 64, z);
    }
}

// Zero-fill residual tail elements beyond the B mel_lens slots (defensive).
__global__ void fill_zero_kernel(float* __restrict__ p, long long n) {
    long long i = (long long)blockIdx.x * blockDim.x + threadIdx.x;
    if (i < n) p[i] = 0.f;
}

extern "C" void kernel_launch(void* const* d_in, const int* in_sizes, int n_in,
                              void* d_out, int out_size) {
    const float* enc = (const float*)d_in[0];
    const int*   dur = (const int*)d_in[1];
    float* out = (float*)d_out;

    // Derive max_len from out_size: out = [B, max_len, D] floats (+ B mel_lens tail).
    const long long row_elems = (long long)NB * ND;   // 6144
    long long total = (long long)out_size;
    int max_len;
    long long tail_elems;
    if (total % row_elems == 0) {
        max_len = (int)(total / row_elems);
        tail_elems = 0;
    } else {
        tail_elems = total % row_elems;                // typically == NB
        max_len = (int)((total - tail_elems) / row_elems);
    }

    const long long body = (long long)NB * max_len * ND;
    float* tail = out + body;

    lr_token_kernel<<<NB * NCH, 128>>>(enc, dur, out, tail,
                                       tail_elems >= NB ? 1 : 0, max_len, NCH);

    if (tail_elems > NB) {
        long long rem = tail_elems - NB;
        fill_zero_kernel<<<(int)((rem + 255) / 256), 256>>>(tail + NB, rem);
    }
}